// round 15
// baseline (speedup 1.0000x reference)
#include <cuda_runtime.h>
#include <cuda_fp16.h>
#include <math.h>

// Problem constants
#define BB   64     // batch
#define NN   100    // nodes
#define LL   32     // feature dim
#define E1   64     // edge hidden / output dim
#define NH   64     // node hidden dim
#define ND   32     // node output dim
#define ALPHAV 0.1f

// Scratch (device globals — no allocation allowed)
__device__ float g_hA[BB*NN*LL];
__device__ float g_hB[BB*NN*LL];
__device__ float g_U [BB*NN*E1];
__device__ float g_V [BB*NN*E1];
__device__ float g_agg[BB*NN*E1];

__device__ __forceinline__ float lrelu(float x) { return fmaxf(x, ALPHAV * x); }

// ---------------------------------------------------------------------------
// Dummy no-op kernel: shifts the ncu capture window (-s 5 -c 1) so the 6th
// launch of the run is the SECOND edge_kernel, making the dominant kernel
// visible to the profiler. Deterministic, no memory traffic.
// ---------------------------------------------------------------------------
__global__ void dummy_kernel() {}

// ---------------------------------------------------------------------------
// h = (x @ lin_w + lin_b).reshape(B, N, L)   -> g_hA
// ---------------------------------------------------------------------------
__global__ void lin_kernel(const float* __restrict__ x,
                           const float* __restrict__ w,
                           const float* __restrict__ b)
{
    int idx = blockIdx.x * blockDim.x + threadIdx.x;   // < B*3200
    int bb  = idx / (NN * LL);
    int o   = idx % (NN * LL);
    float acc = b[o];
    #pragma unroll
    for (int k = 0; k < LL; k++)
        acc = fmaf(x[bb * LL + k], w[k * (NN * LL) + o], acc);
    g_hA[idx] = acc;
}

// ---------------------------------------------------------------------------
// Per-node edge-layer0 partials (step 0 only; later steps fused into node).
// ---------------------------------------------------------------------------
__global__ __launch_bounds__(256)
void uv_kernel(const float* __restrict__ h,
               const float* __restrict__ w0,
               const float* __restrict__ b0)
{
    __shared__ float w0s[64 * 64];     // rows 0..63 of ew0 (16KB)
    __shared__ float hs[16][33];
    int tid = threadIdx.x;
    int n0 = blockIdx.x * 16;

    for (int p = tid; p < 64 * 64; p += 256) w0s[p] = w0[p];
    for (int p = tid; p < 16 * LL; p += 256) {
        int nl = p >> 5, m = p & 31;
        hs[nl][m] = h[(n0 + nl) * LL + m];
    }
    __syncthreads();

    int c     = tid & 63;
    int half  = (tid >> 6) & 1;       // 0 -> U, 1 -> V
    int nh    = tid >> 7;             // node-group 0/1
    const float* wp = w0s + half * (LL * 64);
    float bias = half ? 0.0f : b0[c];

    float acc[8];
    #pragma unroll
    for (int s = 0; s < 8; s++) acc[s] = bias;
    #pragma unroll
    for (int m = 0; m < LL; m++) {
        float wv = wp[m * 64 + c];
        #pragma unroll
        for (int s = 0; s < 8; s++)
            acc[s] = fmaf(hs[nh * 8 + s][m], wv, acc[s]);
    }
    float* dst = half ? g_V : g_U;
    #pragma unroll
    for (int s = 0; s < 8; s++)
        dst[(n0 + nh * 8 + s) * E1 + c] = acc[s];
}

// ---------------------------------------------------------------------------
// Edge kernel — fp16 mma (m16n8k16), one warp per node i, 4 i's/block.
// R12 exact: act0 fp16 in smem, W1 frags from smem (LDS.128 feeds 2 mma),
// bias in registers, single-buffer act0 with two syncwarps per tile.
// ---------------------------------------------------------------------------
__global__ __launch_bounds__(128)
void edge_kernel(const float* __restrict__ h,
                 const float* __restrict__ ew0,   // (65,64): row 64 = dist weights
                 const float* __restrict__ ew1,   // (64,64)
                 const float* __restrict__ eb1)   // (64)
{
    __shared__ __align__(16) float pool[3328];          // 13312 B: hjs / act0 union
    __shared__ __align__(16) __half w1h[4096];          //  8192 B, paired-frag fp16
    __shared__ __align__(16) float dists_s[4][112];     //  1792 B

    const int bb   = blockIdx.y;
    const int i0   = blockIdx.x * 4;
    const int tid  = threadIdx.x;
    const int w    = tid >> 5;
    const int lane = tid & 31;
    const int i    = i0 + w;
    const int q    = lane & 3;        // threadID_in_group (k selector)
    const int r    = lane >> 2;       // groupID (row / col-in-tile)

    // ---- stage hjs (union with act0 pool) ----
    float (*hjs)[33] = reinterpret_cast<float(*)[33]>(pool);
    for (int idx = tid; idx < NN * LL; idx += 128) {
        int j = idx >> 5, m = idx & 31;
        hjs[j][m] = h[(bb * NN + j) * LL + m];
    }
    // ---- repack W1 into paired fp16 fragment order ----
    for (int p4 = tid; p4 < 512; p4 += 128) {
        int kt  = p4 >> 7;            // 0..3
        int rem = p4 & 127;
        int ntp = rem >> 5;           // 0..3
        int ln  = rem & 31;
        int fq  = ln & 3, cr = ln >> 2;
        __half hv[8];
        #pragma unroll
        for (int e = 0; e < 2; e++) {
            int c = (2 * ntp + e) * 8 + cr;
            hv[4*e+0] = __float2half_rn(ew1[(kt * 16 + 2 * fq    ) * 64 + c]);
            hv[4*e+1] = __float2half_rn(ew1[(kt * 16 + 2 * fq + 1) * 64 + c]);
            hv[4*e+2] = __float2half_rn(ew1[(kt * 16 + 2 * fq + 8) * 64 + c]);
            hv[4*e+3] = __float2half_rn(ew1[(kt * 16 + 2 * fq + 9) * 64 + c]);
        }
        *reinterpret_cast<uint4*>(&w1h[p4 * 8]) = *reinterpret_cast<uint4*>(hv);
    }
    __syncthreads();

    // ---- distances for this warp's i ----
    for (int j = lane; j < NN; j += 32) {
        float s = 0.0f;
        #pragma unroll
        for (int m = 0; m < LL; m++) {
            float d = hjs[j][m] - hjs[i][m];
            s = fmaf(d, d, s);
        }
        dists_s[w][j] = sqrtf(s + 1e-12f);
    }
    __syncthreads();   // everyone done reading hjs before act0 overwrites pool

    // ---- per-thread constants ----
    const int kk = 4 * (lane & 15);   // k base this thread fills in act0
    const int tb = lane >> 4;         // 0/1 (which j of the pair per m-step)
    float4 U4  = *reinterpret_cast<const float4*>(&g_U[(bb * NN + i) * E1 + kk]);
    float4 wd4 = *reinterpret_cast<const float4*>(&ew0[64 * E1 + kk]);
    float b1a[8], b1b[8];
    #pragma unroll
    for (int nt = 0; nt < 8; nt++) {
        b1a[nt] = eb1[nt * 8 + 2 * q];
        b1b[nt] = eb1[nt * 8 + 2 * q + 1];
    }

    // act0 fp16 buffer for this warp: 16 rows x 72 halves
    __half* as_h = reinterpret_cast<__half*>(pool) + w * (16 * 72);
    float sa[8][2];
    #pragma unroll
    for (int nt = 0; nt < 8; nt++) { sa[nt][0] = 0.0f; sa[nt][1] = 0.0f; }

    #pragma unroll 1
    for (int jb = 0; jb < 112; jb += 16) {
        // -- act0 for rows jb..jb+15 (fp32 math, fp16 store) --
        #pragma unroll
        for (int m = 0; m < 8; m++) {
            int jl = 2 * m + tb;
            int jg = jb + jl; if (jg > NN - 1) jg = NN - 1;   // clamp pad rows
            float dj = dists_s[w][jg];
            float4 v = *reinterpret_cast<const float4*>(&g_V[(bb * NN + jg) * E1 + kk]);
            float a0 = fmaf(dj, wd4.x, U4.x + v.x); a0 = fmaxf(a0, ALPHAV * a0);
            float a1 = fmaf(dj, wd4.y, U4.y + v.y); a1 = fmaxf(a1, ALPHAV * a1);
            float a2 = fmaf(dj, wd4.z, U4.z + v.z); a2 = fmaxf(a2, ALPHAV * a2);
            float a3 = fmaf(dj, wd4.w, U4.w + v.w); a3 = fmaxf(a3, ALPHAV * a3);
            __half2 h01 = __floats2half2_rn(a0, a1);
            __half2 h23 = __floats2half2_rn(a2, a3);
            uint2 st;
            st.x = *reinterpret_cast<unsigned*>(&h01);
            st.y = *reinterpret_cast<unsigned*>(&h23);
            *reinterpret_cast<uint2*>(&as_h[jl * 72 + kk]) = st;
        }
        __syncwarp();

        // -- D init with bias --
        float d[8][4];
        #pragma unroll
        for (int nt = 0; nt < 8; nt++) {
            d[nt][0] = b1a[nt]; d[nt][1] = b1b[nt];
            d[nt][2] = b1a[nt]; d[nt][3] = b1b[nt];
        }
        // -- 4 k16-chunks x 4 nt-pairs; one LDS.128 feeds two mma --
        #pragma unroll
        for (int kt = 0; kt < 4; kt++) {
            int kb = kt * 16;
            unsigned a0 = *reinterpret_cast<const unsigned*>(&as_h[ r      * 72 + kb + 2 * q    ]);
            unsigned a1 = *reinterpret_cast<const unsigned*>(&as_h[(r + 8) * 72 + kb + 2 * q    ]);
            unsigned a2 = *reinterpret_cast<const unsigned*>(&as_h[ r      * 72 + kb + 2 * q + 8]);
            unsigned a3 = *reinterpret_cast<const unsigned*>(&as_h[(r + 8) * 72 + kb + 2 * q + 8]);
            #pragma unroll
            for (int ntp = 0; ntp < 4; ntp++) {
                uint4 bp = *reinterpret_cast<const uint4*>(
                    &w1h[((kt * 4 + ntp) * 32 + lane) * 8]);
                int nt0 = 2 * ntp, nt1 = nt0 + 1;
                asm volatile(
                    "mma.sync.aligned.m16n8k16.row.col.f32.f16.f16.f32 "
                    "{%0,%1,%2,%3}, {%4,%5,%6,%7}, {%8,%9}, {%0,%1,%2,%3};"
                    : "+f"(d[nt0][0]), "+f"(d[nt0][1]), "+f"(d[nt0][2]), "+f"(d[nt0][3])
                    : "r"(a0), "r"(a1), "r"(a2), "r"(a3), "r"(bp.x), "r"(bp.y));
                asm volatile(
                    "mma.sync.aligned.m16n8k16.row.col.f32.f16.f16.f32 "
                    "{%0,%1,%2,%3}, {%4,%5,%6,%7}, {%8,%9}, {%0,%1,%2,%3};"
                    : "+f"(d[nt1][0]), "+f"(d[nt1][1]), "+f"(d[nt1][2]), "+f"(d[nt1][3])
                    : "r"(a0), "r"(a1), "r"(a2), "r"(a3), "r"(bp.z), "r"(bp.w));
            }
        }
        __syncwarp();   // mma A-reads done before next tile's stores

        // -- epilogue: lrelu + masked row accumulation --
        bool v0 = (jb + r)     < NN;
        bool v1 = (jb + r + 8) < NN;
        #pragma unroll
        for (int nt = 0; nt < 8; nt++) {
            float l0 = fmaxf(d[nt][0], ALPHAV * d[nt][0]);
            float l1 = fmaxf(d[nt][1], ALPHAV * d[nt][1]);
            float l2 = fmaxf(d[nt][2], ALPHAV * d[nt][2]);
            float l3 = fmaxf(d[nt][3], ALPHAV * d[nt][3]);
            if (v0) { sa[nt][0] += l0; sa[nt][1] += l1; }
            if (v1) { sa[nt][0] += l2; sa[nt][1] += l3; }
        }
    }

    // ---- reduce over rows (lanes differing in bits 2..4), write agg ----
    #pragma unroll
    for (int nt = 0; nt < 8; nt++) {
        #pragma unroll
        for (int e = 0; e < 2; e++) {
            float v = sa[nt][e];
            v += __shfl_xor_sync(0xffffffff, v, 4);
            v += __shfl_xor_sync(0xffffffff, v, 8);
            v += __shfl_xor_sync(0xffffffff, v, 16);
            sa[nt][e] = v;
        }
    }
    if (lane < 4) {
        #pragma unroll
        for (int nt = 0; nt < 8; nt++) {
            float2 st = make_float2(sa[nt][0], sa[nt][1]);
            *reinterpret_cast<float2*>(&g_agg[(bb * NN + i) * E1 + nt * 8 + 2 * q]) = st;
        }
    }
}

// ---------------------------------------------------------------------------
// Fused node MLP (+ next-step U/V OR final out-projection). R8 best-known:
// 16 nodes/block, 256 threads, 4 node-accumulators per thread.
// ---------------------------------------------------------------------------
__global__ __launch_bounds__(256)
void node_fused_kernel(const float* __restrict__ h,
                       const float* __restrict__ w0,
                       const float* __restrict__ b0,
                       const float* __restrict__ w1,
                       const float* __restrict__ b1,
                       const float* __restrict__ ew0n,  // next-step edge W0 (65,64)
                       const float* __restrict__ eb0n,  // next-step edge b0 (64)
                       const float* __restrict__ ow,    // out_w (32,3)
                       const float* __restrict__ ob,    // out_b (3)
                       float* __restrict__ hout,
                       float* __restrict__ outp,
                       int last)
{
    __shared__ float w0s[(LL + E1) * NH];  // 24576 B
    __shared__ float w1s[NH * ND];         //  8192 B
    __shared__ float z[16][LL + E1];       //  6144 B
    __shared__ float t0s[16][NH];          //  4096 B
    __shared__ float t1s[16][ND];          //  2048 B

    const int t = threadIdx.x;
    const int g = t >> 6;        // node group 0..3 (4 nodes each)
    const int c = t & 63;        // channel
    const int n0 = blockIdx.x * 16;

    for (int p = t; p < (LL + E1) * NH; p += 256) w0s[p] = w0[p];
    for (int p = t; p < NH * ND; p += 256)        w1s[p] = w1[p];
    for (int p = t; p < 16 * LL; p += 256) {
        int n = p >> 5, m = p & 31;
        z[n][m] = h[(n0 + n) * LL + m];
    }
    for (int p = t; p < 16 * E1; p += 256) {
        int n = p >> 6, m = p & 63;
        z[n][LL + m] = g_agg[(n0 + n) * E1 + m];
    }
    __syncthreads();

    // ---- layer 0: 4 nodes per thread ----
    {
        float acc[4];
        float bv = b0[c];
        #pragma unroll
        for (int s = 0; s < 4; s++) acc[s] = bv;
        #pragma unroll
        for (int m = 0; m < LL + E1; m++) {
            float wv = w0s[m * NH + c];
            #pragma unroll
            for (int s = 0; s < 4; s++)
                acc[s] = fmaf(z[g * 4 + s][m], wv, acc[s]);
        }
        #pragma unroll
        for (int s = 0; s < 4; s++)
            t0s[g * 4 + s][c] = fmaxf(acc[s], ALPHAV * acc[s]);
    }
    __syncthreads();

    // ---- layer 1 (ND=32 outputs; half the channel-threads active) ----
    if (c < ND) {
        float acc[4];
        float bv = b1[c];
        #pragma unroll
        for (int s = 0; s < 4; s++) acc[s] = bv;
        #pragma unroll
        for (int k = 0; k < NH; k++) {
            float wv = w1s[k * ND + c];
            #pragma unroll
            for (int s = 0; s < 4; s++)
                acc[s] = fmaf(t0s[g * 4 + s][k], wv, acc[s]);
        }
        #pragma unroll
        for (int s = 0; s < 4; s++) {
            float v = fmaxf(acc[s], ALPHAV * acc[s]);
            t1s[g * 4 + s][c] = v;
            if (!last) hout[(n0 + g * 4 + s) * ND + c] = v;
        }
    }
    __syncthreads();

    if (last) {
        // ---- final projection: out = tanh(t1 @ ow + ob) ----
        if (t < 48) {
            int n = t / 3, o = t % 3;
            float a = ob[o];
            #pragma unroll
            for (int k = 0; k < ND; k++)
                a = fmaf(t1s[n][k], ow[k * 3 + o], a);
            outp[(n0 + n) * 3 + o] = tanhf(a);
        }
    } else {
        // ---- next-step U/V from t1 (ew0n streamed from L2, coalesced) ----
        float u[4], v4[4];
        float be = eb0n[c];
        #pragma unroll
        for (int s = 0; s < 4; s++) { u[s] = be; v4[s] = 0.0f; }
        #pragma unroll
        for (int m = 0; m < LL; m++) {
            float wu = __ldg(&ew0n[ m       * E1 + c]);
            float wv = __ldg(&ew0n[(LL + m) * E1 + c]);
            #pragma unroll
            for (int s = 0; s < 4; s++) {
                float zz = t1s[g * 4 + s][m];
                u[s]  = fmaf(zz, wu, u[s]);
                v4[s] = fmaf(zz, wv, v4[s]);
            }
        }
        #pragma unroll
        for (int s = 0; s < 4; s++) {
            g_U[(n0 + g * 4 + s) * E1 + c] = u[s];
            g_V[(n0 + g * 4 + s) * E1 + c] = v4[s];
        }
    }
}

// ---------------------------------------------------------------------------
extern "C" void kernel_launch(void* const* d_in, const int* in_sizes, int n_in,
                              void* d_out, int out_size)
{
    const float* x     = (const float*)d_in[0];
    const float* lin_w = (const float*)d_in[1];
    const float* lin_b = (const float*)d_in[2];
    const float* ew0[2] = { (const float*)d_in[3],  (const float*)d_in[11] };
    const float* eb0[2] = { (const float*)d_in[4],  (const float*)d_in[12] };
    const float* ew1[2] = { (const float*)d_in[5],  (const float*)d_in[13] };
    const float* eb1[2] = { (const float*)d_in[6],  (const float*)d_in[14] };
    const float* nw0[2] = { (const float*)d_in[7],  (const float*)d_in[15] };
    const float* nb0[2] = { (const float*)d_in[8],  (const float*)d_in[16] };
    const float* nw1[2] = { (const float*)d_in[9],  (const float*)d_in[17] };
    const float* nb1[2] = { (const float*)d_in[10], (const float*)d_in[18] };
    const float* out_w = (const float*)d_in[19];
    const float* out_b = (const float*)d_in[20];
    float* out = (float*)d_out;

    float *hA, *hB;
    cudaGetSymbolAddress((void**)&hA, g_hA);
    cudaGetSymbolAddress((void**)&hB, g_hB);

    // Launch #1: dummy — shifts ncu's -s 5 -c 1 window so launch #6 (the
    // captured one) is the second edge_kernel instead of the last node kernel.
    dummy_kernel<<<1, 32>>>();

    lin_kernel<<<(BB * NN * LL) / 256, 256>>>(x, lin_w, lin_b);

    // step 0
    uv_kernel<<<(BB * NN) / 16, 256>>>(hA, ew0[0], eb0[0]);
    dim3 eg(NN / 4, BB);
    edge_kernel<<<eg, 128>>>(hA, ew0[0], ew1[0], eb1[0]);
    // node MLP 0 + U/V for step 1 (fused)
    node_fused_kernel<<<(BB * NN) / 16, 256>>>(hA, nw0[0], nb0[0], nw1[0], nb1[0],
                                               ew0[1], eb0[1], out_w, out_b,
                                               hB, out, 0);
    // step 1
    edge_kernel<<<eg, 128>>>(hB, ew0[1], ew1[1], eb1[1]);
    // node MLP 1 + final projection (fused)
    node_fused_kernel<<<(BB * NN) / 16, 256>>>(hB, nw0[1], nb0[1], nw1[1], nb1[1],
                                               ew0[1], eb0[1], out_w, out_b,
                                               hB, out, 1);
}

// round 16
// speedup vs baseline: 1.6451x; 1.6451x over previous
#include <cuda_runtime.h>
#include <cuda_fp16.h>
#include <math.h>

// Problem constants
#define BB   64     // batch
#define NN   100    // nodes
#define LL   32     // feature dim
#define E1   64     // edge hidden / output dim
#define NH   64     // node hidden dim
#define ND   32     // node output dim
#define ALPHAV 0.1f

// Scratch (device globals — no allocation allowed)
__device__ float g_hA[BB*NN*LL];
__device__ float g_hB[BB*NN*LL];
__device__ float g_U [BB*NN*E1];
__device__ float g_V [BB*NN*E1];
__device__ float g_agg[BB*NN*E1];

__device__ __forceinline__ float lrelu(float x) { return fmaxf(x, ALPHAV * x); }

__device__ __forceinline__ void ldm4(unsigned &a0, unsigned &a1,
                                     unsigned &a2, unsigned &a3, unsigned addr)
{
    asm volatile("ldmatrix.sync.aligned.m8n8.x4.shared.b16 {%0,%1,%2,%3}, [%4];"
                 : "=r"(a0), "=r"(a1), "=r"(a2), "=r"(a3) : "r"(addr));
}

// ---------------------------------------------------------------------------
// h = (x @ lin_w + lin_b).reshape(B, N, L)   -> g_hA
// ---------------------------------------------------------------------------
__global__ void lin_kernel(const float* __restrict__ x,
                           const float* __restrict__ w,
                           const float* __restrict__ b)
{
    int idx = blockIdx.x * blockDim.x + threadIdx.x;   // < B*3200
    int bb  = idx / (NN * LL);
    int o   = idx % (NN * LL);
    float acc = b[o];
    #pragma unroll
    for (int k = 0; k < LL; k++)
        acc = fmaf(x[bb * LL + k], w[k * (NN * LL) + o], acc);
    g_hA[idx] = acc;
}

// ---------------------------------------------------------------------------
// Per-node edge-layer0 partials (step 0 only; later steps fused into node).
// ---------------------------------------------------------------------------
__global__ __launch_bounds__(256)
void uv_kernel(const float* __restrict__ h,
               const float* __restrict__ w0,
               const float* __restrict__ b0)
{
    __shared__ float w0s[64 * 64];     // rows 0..63 of ew0 (16KB)
    __shared__ float hs[16][33];
    int tid = threadIdx.x;
    int n0 = blockIdx.x * 16;

    for (int p = tid; p < 64 * 64; p += 256) w0s[p] = w0[p];
    for (int p = tid; p < 16 * LL; p += 256) {
        int nl = p >> 5, m = p & 31;
        hs[nl][m] = h[(n0 + nl) * LL + m];
    }
    __syncthreads();

    int c     = tid & 63;
    int half  = (tid >> 6) & 1;       // 0 -> U, 1 -> V
    int nh    = tid >> 7;             // node-group 0/1
    const float* wp = w0s + half * (LL * 64);
    float bias = half ? 0.0f : b0[c];

    float acc[8];
    #pragma unroll
    for (int s = 0; s < 8; s++) acc[s] = bias;
    #pragma unroll
    for (int m = 0; m < LL; m++) {
        float wv = wp[m * 64 + c];
        #pragma unroll
        for (int s = 0; s < 8; s++)
            acc[s] = fmaf(hs[nh * 8 + s][m], wv, acc[s]);
    }
    float* dst = half ? g_V : g_U;
    #pragma unroll
    for (int s = 0; s < 8; s++)
        dst[(n0 + nh * 8 + s) * E1 + c] = acc[s];
}

// ---------------------------------------------------------------------------
// Edge kernel — fp16 mma (m16n8k16), one warp per node i, 4 i's/block.
// Instruction-diet version of R12:
//   * kt=0 mma takes the bias as its C operand (kills 32 MOVs/tile)
//   * epilogue lrelu+accumulate fused: sa = fma(0.55,d,sa); sa = fma(0.45,|d|,sa)
//   * A-fragments via ldmatrix.x4 (16 LDS.32 -> 4 instr/tile)
//   * last (partial) tile specialized out of the mainloop
// ---------------------------------------------------------------------------
__global__ __launch_bounds__(128)
void edge_kernel(const float* __restrict__ h,
                 const float* __restrict__ ew0,   // (65,64): row 64 = dist weights
                 const float* __restrict__ ew1,   // (64,64)
                 const float* __restrict__ eb1)   // (64)
{
    __shared__ __align__(16) float pool[3328];          // 13312 B: hjs / act0 union
    __shared__ __align__(16) __half w1h[4096];          //  8192 B, paired-frag fp16
    __shared__ __align__(16) float dists_s[4][112];     //  1792 B

    const int bb   = blockIdx.y;
    const int i0   = blockIdx.x * 4;
    const int tid  = threadIdx.x;
    const int w    = tid >> 5;
    const int lane = tid & 31;
    const int i    = i0 + w;
    const int q    = lane & 3;        // threadID_in_group (k selector)
    const int r    = lane >> 2;       // groupID (row / col-in-tile)

    // ---- stage hjs (union with act0 pool) ----
    float (*hjs)[33] = reinterpret_cast<float(*)[33]>(pool);
    for (int idx = tid; idx < NN * LL; idx += 128) {
        int j = idx >> 5, m = idx & 31;
        hjs[j][m] = h[(bb * NN + j) * LL + m];
    }
    // ---- repack W1 into paired fp16 fragment order ----
    for (int p4 = tid; p4 < 512; p4 += 128) {
        int kt  = p4 >> 7;            // 0..3
        int rem = p4 & 127;
        int ntp = rem >> 5;           // 0..3
        int ln  = rem & 31;
        int fq  = ln & 3, cr = ln >> 2;
        __half hv[8];
        #pragma unroll
        for (int e = 0; e < 2; e++) {
            int c = (2 * ntp + e) * 8 + cr;
            hv[4*e+0] = __float2half_rn(ew1[(kt * 16 + 2 * fq    ) * 64 + c]);
            hv[4*e+1] = __float2half_rn(ew1[(kt * 16 + 2 * fq + 1) * 64 + c]);
            hv[4*e+2] = __float2half_rn(ew1[(kt * 16 + 2 * fq + 8) * 64 + c]);
            hv[4*e+3] = __float2half_rn(ew1[(kt * 16 + 2 * fq + 9) * 64 + c]);
        }
        *reinterpret_cast<uint4*>(&w1h[p4 * 8]) = *reinterpret_cast<uint4*>(hv);
    }
    __syncthreads();

    // ---- distances for this warp's i ----
    for (int j = lane; j < NN; j += 32) {
        float s = 0.0f;
        #pragma unroll
        for (int m = 0; m < LL; m++) {
            float d = hjs[j][m] - hjs[i][m];
            s = fmaf(d, d, s);
        }
        dists_s[w][j] = sqrtf(s + 1e-12f);
    }
    __syncthreads();   // everyone done reading hjs before act0 overwrites pool

    // ---- per-thread constants ----
    const int kk = 4 * (lane & 15);   // k base this thread fills in act0
    const int tb = lane >> 4;         // 0/1 (which j of the pair per m-step)
    float4 U4  = *reinterpret_cast<const float4*>(&g_U[(bb * NN + i) * E1 + kk]);
    float4 wd4 = *reinterpret_cast<const float4*>(&ew0[64 * E1 + kk]);
    float b1a[8], b1b[8];
    #pragma unroll
    for (int nt = 0; nt < 8; nt++) {
        b1a[nt] = eb1[nt * 8 + 2 * q];
        b1b[nt] = eb1[nt * 8 + 2 * q + 1];
    }

    // act0 fp16 buffer for this warp: 16 rows x 72 halves
    __half* as_h = reinterpret_cast<__half*>(pool) + w * (16 * 72);
    // ldmatrix per-thread base address (bytes): row (lane&15), col-half (lane>>4)*8
    unsigned lm_base = (unsigned)__cvta_generic_to_shared(as_h)
                     + (lane & 15) * 144 + (lane >> 4) * 16;

    const float* Vb = g_V + bb * NN * E1;
    const float* dw = dists_s[w];

    float sa[8][2];
    #pragma unroll
    for (int nt = 0; nt < 8; nt++) { sa[nt][0] = 0.0f; sa[nt][1] = 0.0f; }

    float d[8][4];

    // mma core for the current act0 buffer: kt=0 seeds with bias via C operand
    auto mma_tile = [&]() {
        unsigned a0, a1, a2, a3;
        ldm4(a0, a1, a2, a3, lm_base);
        #pragma unroll
        for (int ntp = 0; ntp < 4; ntp++) {
            uint4 bp = *reinterpret_cast<const uint4*>(&w1h[(ntp * 32 + lane) * 8]);
            int nt0 = 2 * ntp, nt1 = nt0 + 1;
            asm volatile(
                "mma.sync.aligned.m16n8k16.row.col.f32.f16.f16.f32 "
                "{%0,%1,%2,%3}, {%4,%5,%6,%7}, {%8,%9}, {%10,%11,%10,%11};"
                : "=f"(d[nt0][0]), "=f"(d[nt0][1]), "=f"(d[nt0][2]), "=f"(d[nt0][3])
                : "r"(a0), "r"(a1), "r"(a2), "r"(a3), "r"(bp.x), "r"(bp.y),
                  "f"(b1a[nt0]), "f"(b1b[nt0]));
            asm volatile(
                "mma.sync.aligned.m16n8k16.row.col.f32.f16.f16.f32 "
                "{%0,%1,%2,%3}, {%4,%5,%6,%7}, {%8,%9}, {%10,%11,%10,%11};"
                : "=f"(d[nt1][0]), "=f"(d[nt1][1]), "=f"(d[nt1][2]), "=f"(d[nt1][3])
                : "r"(a0), "r"(a1), "r"(a2), "r"(a3), "r"(bp.z), "r"(bp.w),
                  "f"(b1a[nt1]), "f"(b1b[nt1]));
        }
        #pragma unroll
        for (int kt = 1; kt < 4; kt++) {
            ldm4(a0, a1, a2, a3, lm_base + kt * 32);
            #pragma unroll
            for (int ntp = 0; ntp < 4; ntp++) {
                uint4 bp = *reinterpret_cast<const uint4*>(
                    &w1h[((kt * 4 + ntp) * 32 + lane) * 8]);
                int nt0 = 2 * ntp, nt1 = nt0 + 1;
                asm volatile(
                    "mma.sync.aligned.m16n8k16.row.col.f32.f16.f16.f32 "
                    "{%0,%1,%2,%3}, {%4,%5,%6,%7}, {%8,%9}, {%0,%1,%2,%3};"
                    : "+f"(d[nt0][0]), "+f"(d[nt0][1]), "+f"(d[nt0][2]), "+f"(d[nt0][3])
                    : "r"(a0), "r"(a1), "r"(a2), "r"(a3), "r"(bp.x), "r"(bp.y));
                asm volatile(
                    "mma.sync.aligned.m16n8k16.row.col.f32.f16.f16.f32 "
                    "{%0,%1,%2,%3}, {%4,%5,%6,%7}, {%8,%9}, {%0,%1,%2,%3};"
                    : "+f"(d[nt1][0]), "+f"(d[nt1][1]), "+f"(d[nt1][2]), "+f"(d[nt1][3])
                    : "r"(a0), "r"(a1), "r"(a2), "r"(a3), "r"(bp.z), "r"(bp.w));
            }
        }
    };

    // ---- main loop: tiles 0..5 are fully valid (rows jb..jb+15 < 100) ----
    #pragma unroll 1
    for (int t6 = 0; t6 < 6; t6++) {
        int jb = t6 * 16;
        // -- act0 build (no clamp needed) --
        #pragma unroll
        for (int m = 0; m < 8; m++) {
            int jl = 2 * m + tb;
            int jg = jb + jl;
            float dj = dw[jg];
            float4 v = *reinterpret_cast<const float4*>(&Vb[jg * E1 + kk]);
            float a0 = fmaf(dj, wd4.x, U4.x + v.x); a0 = fmaxf(a0, ALPHAV * a0);
            float a1 = fmaf(dj, wd4.y, U4.y + v.y); a1 = fmaxf(a1, ALPHAV * a1);
            float a2 = fmaf(dj, wd4.z, U4.z + v.z); a2 = fmaxf(a2, ALPHAV * a2);
            float a3 = fmaf(dj, wd4.w, U4.w + v.w); a3 = fmaxf(a3, ALPHAV * a3);
            __half2 h01 = __floats2half2_rn(a0, a1);
            __half2 h23 = __floats2half2_rn(a2, a3);
            uint2 st;
            st.x = *reinterpret_cast<unsigned*>(&h01);
            st.y = *reinterpret_cast<unsigned*>(&h23);
            *reinterpret_cast<uint2*>(&as_h[jl * 72 + kk]) = st;
        }
        __syncwarp();
        mma_tile();
        __syncwarp();   // mma A-reads done before next tile's stores

        // -- fused lrelu+accumulate: sa += 0.55*d + 0.45*|d| --
        #pragma unroll
        for (int nt = 0; nt < 8; nt++) {
            sa[nt][0] = fmaf(0.55f, d[nt][0], sa[nt][0]);
            sa[nt][0] = fmaf(0.45f, fabsf(d[nt][0]), sa[nt][0]);
            sa[nt][1] = fmaf(0.55f, d[nt][1], sa[nt][1]);
            sa[nt][1] = fmaf(0.45f, fabsf(d[nt][1]), sa[nt][1]);
            sa[nt][0] = fmaf(0.55f, d[nt][2], sa[nt][0]);
            sa[nt][0] = fmaf(0.45f, fabsf(d[nt][2]), sa[nt][0]);
            sa[nt][1] = fmaf(0.55f, d[nt][3], sa[nt][1]);
            sa[nt][1] = fmaf(0.45f, fabsf(d[nt][3]), sa[nt][1]);
        }
    }

    // ---- last tile (jb=96): rows 96..99 valid only ----
    {
        const int jb = 96;
        #pragma unroll
        for (int m = 0; m < 8; m++) {
            int jl = 2 * m + tb;
            int jg = jb + jl; if (jg > NN - 1) jg = NN - 1;
            float dj = dw[jg];
            float4 v = *reinterpret_cast<const float4*>(&Vb[jg * E1 + kk]);
            float a0 = fmaf(dj, wd4.x, U4.x + v.x); a0 = fmaxf(a0, ALPHAV * a0);
            float a1 = fmaf(dj, wd4.y, U4.y + v.y); a1 = fmaxf(a1, ALPHAV * a1);
            float a2 = fmaf(dj, wd4.z, U4.z + v.z); a2 = fmaxf(a2, ALPHAV * a2);
            float a3 = fmaf(dj, wd4.w, U4.w + v.w); a3 = fmaxf(a3, ALPHAV * a3);
            __half2 h01 = __floats2half2_rn(a0, a1);
            __half2 h23 = __floats2half2_rn(a2, a3);
            uint2 st;
            st.x = *reinterpret_cast<unsigned*>(&h01);
            st.y = *reinterpret_cast<unsigned*>(&h23);
            *reinterpret_cast<uint2*>(&as_h[jl * 72 + kk]) = st;
        }
        __syncwarp();
        mma_tile();

        if (r < 4) {   // only rows 96..99 (d[nt][0,1]) are real
            #pragma unroll
            for (int nt = 0; nt < 8; nt++) {
                sa[nt][0] = fmaf(0.55f, d[nt][0], sa[nt][0]);
                sa[nt][0] = fmaf(0.45f, fabsf(d[nt][0]), sa[nt][0]);
                sa[nt][1] = fmaf(0.55f, d[nt][1], sa[nt][1]);
                sa[nt][1] = fmaf(0.45f, fabsf(d[nt][1]), sa[nt][1]);
            }
        }
    }

    // ---- reduce over rows (lanes differing in bits 2..4), write agg ----
    #pragma unroll
    for (int nt = 0; nt < 8; nt++) {
        #pragma unroll
        for (int e = 0; e < 2; e++) {
            float v = sa[nt][e];
            v += __shfl_xor_sync(0xffffffff, v, 4);
            v += __shfl_xor_sync(0xffffffff, v, 8);
            v += __shfl_xor_sync(0xffffffff, v, 16);
            sa[nt][e] = v;
        }
    }
    if (lane < 4) {
        #pragma unroll
        for (int nt = 0; nt < 8; nt++) {
            float2 st = make_float2(sa[nt][0], sa[nt][1]);
            *reinterpret_cast<float2*>(&g_agg[(bb * NN + i) * E1 + nt * 8 + 2 * q]) = st;
        }
    }
}

// ---------------------------------------------------------------------------
// Fused node MLP (+ next-step U/V OR final out-projection). R8 best-known:
// 16 nodes/block, 256 threads, 4 node-accumulators per thread.
// ---------------------------------------------------------------------------
__global__ __launch_bounds__(256)
void node_fused_kernel(const float* __restrict__ h,
                       const float* __restrict__ w0,
                       const float* __restrict__ b0,
                       const float* __restrict__ w1,
                       const float* __restrict__ b1,
                       const float* __restrict__ ew0n,  // next-step edge W0 (65,64)
                       const float* __restrict__ eb0n,  // next-step edge b0 (64)
                       const float* __restrict__ ow,    // out_w (32,3)
                       const float* __restrict__ ob,    // out_b (3)
                       float* __restrict__ hout,
                       float* __restrict__ outp,
                       int last)
{
    __shared__ float w0s[(LL + E1) * NH];  // 24576 B
    __shared__ float w1s[NH * ND];         //  8192 B
    __shared__ float z[16][LL + E1];       //  6144 B
    __shared__ float t0s[16][NH];          //  4096 B
    __shared__ float t1s[16][ND];          //  2048 B

    const int t = threadIdx.x;
    const int g = t >> 6;        // node group 0..3 (4 nodes each)
    const int c = t & 63;        // channel
    const int n0 = blockIdx.x * 16;

    for (int p = t; p < (LL + E1) * NH; p += 256) w0s[p] = w0[p];
    for (int p = t; p < NH * ND; p += 256)        w1s[p] = w1[p];
    for (int p = t; p < 16 * LL; p += 256) {
        int n = p >> 5, m = p & 31;
        z[n][m] = h[(n0 + n) * LL + m];
    }
    for (int p = t; p < 16 * E1; p += 256) {
        int n = p >> 6, m = p & 63;
        z[n][LL + m] = g_agg[(n0 + n) * E1 + m];
    }
    __syncthreads();

    // ---- layer 0: 4 nodes per thread ----
    {
        float acc[4];
        float bv = b0[c];
        #pragma unroll
        for (int s = 0; s < 4; s++) acc[s] = bv;
        #pragma unroll
        for (int m = 0; m < LL + E1; m++) {
            float wv = w0s[m * NH + c];
            #pragma unroll
            for (int s = 0; s < 4; s++)
                acc[s] = fmaf(z[g * 4 + s][m], wv, acc[s]);
        }
        #pragma unroll
        for (int s = 0; s < 4; s++)
            t0s[g * 4 + s][c] = fmaxf(acc[s], ALPHAV * acc[s]);
    }
    __syncthreads();

    // ---- layer 1 (ND=32 outputs; half the channel-threads active) ----
    if (c < ND) {
        float acc[4];
        float bv = b1[c];
        #pragma unroll
        for (int s = 0; s < 4; s++) acc[s] = bv;
        #pragma unroll
        for (int k = 0; k < NH; k++) {
            float wv = w1s[k * ND + c];
            #pragma unroll
            for (int s = 0; s < 4; s++)
                acc[s] = fmaf(t0s[g * 4 + s][k], wv, acc[s]);
        }
        #pragma unroll
        for (int s = 0; s < 4; s++) {
            float v = fmaxf(acc[s], ALPHAV * acc[s]);
            t1s[g * 4 + s][c] = v;
            if (!last) hout[(n0 + g * 4 + s) * ND + c] = v;
        }
    }
    __syncthreads();

    if (last) {
        // ---- final projection: out = tanh(t1 @ ow + ob) ----
        if (t < 48) {
            int n = t / 3, o = t % 3;
            float a = ob[o];
            #pragma unroll
            for (int k = 0; k < ND; k++)
                a = fmaf(t1s[n][k], ow[k * 3 + o], a);
            outp[(n0 + n) * 3 + o] = tanhf(a);
        }
    } else {
        // ---- next-step U/V from t1 (ew0n streamed from L2, coalesced) ----
        float u[4], v4[4];
        float be = eb0n[c];
        #pragma unroll
        for (int s = 0; s < 4; s++) { u[s] = be; v4[s] = 0.0f; }
        #pragma unroll
        for (int m = 0; m < LL; m++) {
            float wu = __ldg(&ew0n[ m       * E1 + c]);
            float wv = __ldg(&ew0n[(LL + m) * E1 + c]);
            #pragma unroll
            for (int s = 0; s < 4; s++) {
                float zz = t1s[g * 4 + s][m];
                u[s]  = fmaf(zz, wu, u[s]);
                v4[s] = fmaf(zz, wv, v4[s]);
            }
        }
        #pragma unroll
        for (int s = 0; s < 4; s++) {
            g_U[(n0 + g * 4 + s) * E1 + c] = u[s];
            g_V[(n0 + g * 4 + s) * E1 + c] = v4[s];
        }
    }
}

// ---------------------------------------------------------------------------
extern "C" void kernel_launch(void* const* d_in, const int* in_sizes, int n_in,
                              void* d_out, int out_size)
{
    const float* x     = (const float*)d_in[0];
    const float* lin_w = (const float*)d_in[1];
    const float* lin_b = (const float*)d_in[2];
    const float* ew0[2] = { (const float*)d_in[3],  (const float*)d_in[11] };
    const float* eb0[2] = { (const float*)d_in[4],  (const float*)d_in[12] };
    const float* ew1[2] = { (const float*)d_in[5],  (const float*)d_in[13] };
    const float* eb1[2] = { (const float*)d_in[6],  (const float*)d_in[14] };
    const float* nw0[2] = { (const float*)d_in[7],  (const float*)d_in[15] };
    const float* nb0[2] = { (const float*)d_in[8],  (const float*)d_in[16] };
    const float* nw1[2] = { (const float*)d_in[9],  (const float*)d_in[17] };
    const float* nb1[2] = { (const float*)d_in[10], (const float*)d_in[18] };
    const float* out_w = (const float*)d_in[19];
    const float* out_b = (const float*)d_in[20];
    float* out = (float*)d_out;

    float *hA, *hB;
    cudaGetSymbolAddress((void**)&hA, g_hA);
    cudaGetSymbolAddress((void**)&hB, g_hB);

    lin_kernel<<<(BB * NN * LL) / 256, 256>>>(x, lin_w, lin_b);

    // step 0
    uv_kernel<<<(BB * NN) / 16, 256>>>(hA, ew0[0], eb0[0]);
    dim3 eg(NN / 4, BB);
    edge_kernel<<<eg, 128>>>(hA, ew0[0], ew1[0], eb1[0]);
    // node MLP 0 + U/V for step 1 (fused)
    node_fused_kernel<<<(BB * NN) / 16, 256>>>(hA, nw0[0], nb0[0], nw1[0], nb1[0],
                                               ew0[1], eb0[1], out_w, out_b,
                                               hB, out, 0);
    // step 1
    edge_kernel<<<eg, 128>>>(hB, ew0[1], ew1[1], eb1[1]);
    // node MLP 1 + final projection (fused)
    node_fused_kernel<<<(BB * NN) / 16, 256>>>(hB, nw0[1], nb0[1], nw1[1], nb1[1],
                                               ew0[1], eb0[1], out_w, out_b,
                                               hB, out, 1);
}